// round 7
// baseline (speedup 1.0000x reference)
#include <cuda_runtime.h>
#include <math.h>

#define Bz 32
#define Tz 512
#define Iz 256
#define Hz 1024
#define G4 4096
#define Oz 512
#define TR 500

typedef unsigned long long ull;

// ---- packed f32x2 helpers (sm_103a) ----
__device__ __forceinline__ ull pack2(float x, float y) {
    ull r; asm("mov.b64 %0, {%1,%2};" : "=l"(r) : "f"(x), "f"(y)); return r;
}
__device__ __forceinline__ void unpack2(ull v, float& x, float& y) {
    asm("mov.b64 {%0,%1}, %2;" : "=f"(x), "=f"(y) : "l"(v));
}
__device__ __forceinline__ void fma2(ull& d, ull a, ull b) {
    asm("fma.rn.f32x2 %0, %1, %2, %0;" : "+l"(d) : "l"(a), "l"(b));
}
__device__ __forceinline__ ull add2(ull a, ull b) {
    ull r; asm("add.rn.f32x2 %0, %1, %2;" : "=l"(r) : "l"(a), "l"(b)); return r;
}

// ---- scratch (device globals: allocation-free) ----
__device__ __align__(16) float g_xt[Tz * Bz * Iz];
__device__ __align__(16) float g_xg[Tz * Bz * G4];
__device__ __align__(16) float g_h1[Tz * Bz * Hz];
__device__ __align__(16) float g_h2[Tz * Bz * Hz];

// ---- software grid barrier (all 128 blocks co-resident: 1 block/SM, 128<148) ----
__device__ unsigned g_bar_count = 0;
__device__ volatile unsigned g_bar_gen = 0;

__device__ __forceinline__ void grid_sync() {
    __threadfence();
    __syncthreads();
    if (threadIdx.x == 0) {
        unsigned gen = g_bar_gen;
        if (atomicAdd(&g_bar_count, 1u) == gridDim.x - 1u) {
            atomicExch(&g_bar_count, 0u);
            __threadfence();
            g_bar_gen = gen + 1u;
        } else {
            while (g_bar_gen == gen) { __nanosleep(64); }
        }
        __threadfence();
    }
    __syncthreads();
}

// ---------------------------------------------------------------------------
// Transpose x: [B,T,I] -> time-major [T,B,I] (float4)
// ---------------------------------------------------------------------------
__global__ void transpose_x(const float4* __restrict__ x, float4* __restrict__ xt) {
    int idx = blockIdx.x * blockDim.x + threadIdx.x;   // < 1048576
    int i4 = idx & 63;
    int m  = idx >> 6;
    int t  = m >> 5;
    int b  = m & 31;
    xt[idx] = x[(b * Tz + t) * (Iz / 4) + i4];
}

// ---------------------------------------------------------------------------
// SGEMM (TN): C[m][n] = sum_k Arow(m)[k] * W[n][k] + b1[n] (+ b2[n])
// 128x128 tile, BK=16, 256 threads, 8x8 per thread, f32x2 packed along m.
// MODE 0: Arow(m) = A + m*K; MODE 1: Arow(m) = A + (t*B+b)*K, m = b*TR + t.
// ---------------------------------------------------------------------------
template <int MODE>
__global__ __launch_bounds__(256, 2)
void sgemm_tn(const float* __restrict__ A, const float* __restrict__ W,
              const float* __restrict__ b1, const float* __restrict__ b2,
              float* __restrict__ C, int M, int N, int K) {
    __shared__ __align__(16) float As[16][128];
    __shared__ __align__(16) float Bs[16][128];

    const int tid = threadIdx.x;
    const int ty = tid >> 4, tx = tid & 15;
    const int m0 = blockIdx.y * 128, n0 = blockIdx.x * 128;

    ull acc[4][8];
#pragma unroll
    for (int i = 0; i < 4; i++)
#pragma unroll
        for (int j = 0; j < 8; j++) acc[i][j] = 0ULL;

    const float* arow[2];
    int arr[2], acc4[2];
#pragma unroll
    for (int i = 0; i < 2; i++) {
        int item = tid + 256 * i;
        int r = item >> 2, c4 = item & 3;
        arr[i] = r; acc4[i] = c4;
        int m = m0 + r;
        if (MODE == 1) {
            int bb = m / TR, t = m - bb * TR;
            arow[i] = A + (long long)(t * Bz + bb) * K;
        } else {
            arow[i] = A + (long long)m * K;
        }
    }
    const float* wrow[2];
#pragma unroll
    for (int i = 0; i < 2; i++) wrow[i] = W + (long long)(n0 + arr[i]) * K;

    for (int k0 = 0; k0 < K; k0 += 16) {
        __syncthreads();
#pragma unroll
        for (int i = 0; i < 2; i++) {
            int r = arr[i], c4 = acc4[i];
            float4 va = *(const float4*)(arow[i] + k0 + c4 * 4);
            As[c4 * 4 + 0][r] = va.x; As[c4 * 4 + 1][r] = va.y;
            As[c4 * 4 + 2][r] = va.z; As[c4 * 4 + 3][r] = va.w;
            float4 vb = *(const float4*)(wrow[i] + k0 + c4 * 4);
            Bs[c4 * 4 + 0][r] = vb.x; Bs[c4 * 4 + 1][r] = vb.y;
            Bs[c4 * 4 + 2][r] = vb.z; Bs[c4 * 4 + 3][r] = vb.w;
        }
        __syncthreads();
#pragma unroll
        for (int k = 0; k < 16; k++) {
            ull a2[4];
#pragma unroll
            for (int mp = 0; mp < 4; mp++)
                a2[mp] = *(const ull*)&As[k][ty * 8 + mp * 2];
            float4 bv0 = *(const float4*)&Bs[k][tx * 8];
            float4 bv1 = *(const float4*)&Bs[k][tx * 8 + 4];
            ull bd[8];
            bd[0] = pack2(bv0.x, bv0.x); bd[1] = pack2(bv0.y, bv0.y);
            bd[2] = pack2(bv0.z, bv0.z); bd[3] = pack2(bv0.w, bv0.w);
            bd[4] = pack2(bv1.x, bv1.x); bd[5] = pack2(bv1.y, bv1.y);
            bd[6] = pack2(bv1.z, bv1.z); bd[7] = pack2(bv1.w, bv1.w);
#pragma unroll
            for (int mp = 0; mp < 4; mp++)
#pragma unroll
                for (int n = 0; n < 8; n++) fma2(acc[mp][n], a2[mp], bd[n]);
        }
    }

    float bb[8];
#pragma unroll
    for (int n = 0; n < 8; n++) {
        int col = n0 + tx * 8 + n;
        bb[n] = b1[col] + (b2 ? b2[col] : 0.0f);
    }
#pragma unroll
    for (int mp = 0; mp < 4; mp++) {
        float lo[8], hi[8];
#pragma unroll
        for (int n = 0; n < 8; n++) unpack2(acc[mp][n], lo[n], hi[n]);
        int row0 = m0 + ty * 8 + mp * 2;
        float* c0 = C + (long long)row0 * N + n0 + tx * 8;
        float* c1 = c0 + N;
        float o0[8], o1[8];
#pragma unroll
        for (int n = 0; n < 8; n++) { o0[n] = lo[n] + bb[n]; o1[n] = hi[n] + bb[n]; }
        *(float4*)(c0)     = make_float4(o0[0], o0[1], o0[2], o0[3]);
        *(float4*)(c0 + 4) = make_float4(o0[4], o0[5], o0[6], o0[7]);
        *(float4*)(c1)     = make_float4(o1[0], o1[1], o1[2], o1[3]);
        *(float4*)(c1 + 4) = make_float4(o1[4], o1[5], o1[6], o1[7]);
    }
}

// ---------------------------------------------------------------------------
// Persistent LSTM recurrence: ONE launch for all 512 steps of a layer.
// 128 blocks x 256 threads. Warp u owns hidden unit j = 8*blockIdx + u (all 4
// gates). Lane owns interleaved k-slice k = 64m + 2*lane (+0/1), m=0..15, so
// W_hh stays in 128 registers per thread for the whole sequence.
// Per step: stage h[t-1] to smem (128KB), dot via fma.rn.f32x2, butterfly-shfl
// reduce over lanes (result for batch b lands on lane b), fused pointwise with
// c in-register, STG h[t], grid barrier.
// ---------------------------------------------------------------------------
__global__ __launch_bounds__(256, 1)
void lstm_recurrence(const float* __restrict__ xg,   // [T][B][4H]
                     const float* __restrict__ Whh,  // [4H][H]
                     float* __restrict__ hout) {     // [T][B][H]
    extern __shared__ float sh[];                    // [32][1024] = 128KB
    const int tid = threadIdx.x;
    const int lane = tid & 31;
    const int u = tid >> 5;
    const int j = blockIdx.x * 8 + u;

    // load W_hh slice into registers: (i,f) and (g,o) packed pairs
    ull w01[32], w23[32];
    {
        const float2* Wi = (const float2*)(Whh + (size_t)j * Hz);
        const float2* Wf = (const float2*)(Whh + (size_t)(Hz + j) * Hz);
        const float2* Wg = (const float2*)(Whh + (size_t)(2 * Hz + j) * Hz);
        const float2* Wo = (const float2*)(Whh + (size_t)(3 * Hz + j) * Hz);
#pragma unroll
        for (int m = 0; m < 16; m++) {
            float2 a = Wi[32 * m + lane], b = Wf[32 * m + lane];
            w01[2 * m]     = pack2(a.x, b.x);
            w01[2 * m + 1] = pack2(a.y, b.y);
            float2 c = Wg[32 * m + lane], d = Wo[32 * m + lane];
            w23[2 * m]     = pack2(c.x, d.x);
            w23[2 * m + 1] = pack2(c.y, d.y);
        }
    }

    float creg = 0.0f;   // c[b=lane][j], lives in a register all 512 steps
    float4* shv = (float4*)sh;

    for (int t = 0; t < Tz; t++) {
        if (t > 0) {
            const float4* hp = (const float4*)(hout + (size_t)(t - 1) * Bz * Hz);
#pragma unroll 4
            for (int i = 0; i < 32; i++)
                shv[tid + 256 * i] = hp[tid + 256 * i];
        }
        __syncthreads();

        ull my01 = 0ULL, my23 = 0ULL;
        if (t > 0) {
#pragma unroll 1
            for (int b = 0; b < 32; b++) {
                ull p01 = 0ULL, p23 = 0ULL;
                const float2* hb = (const float2*)(sh + b * Hz);
#pragma unroll
                for (int m = 0; m < 16; m++) {
                    float2 h2 = hb[32 * m + lane];
                    ull hx = pack2(h2.x, h2.x);
                    ull hy = pack2(h2.y, h2.y);
                    fma2(p01, hx, w01[2 * m]);
                    fma2(p23, hx, w23[2 * m]);
                    fma2(p01, hy, w01[2 * m + 1]);
                    fma2(p23, hy, w23[2 * m + 1]);
                }
#pragma unroll
                for (int off = 16; off > 0; off >>= 1) {
                    p01 = add2(p01, __shfl_xor_sync(0xffffffffu, p01, off));
                    p23 = add2(p23, __shfl_xor_sync(0xffffffffu, p23, off));
                }
                if (lane == b) { my01 = p01; my23 = p23; }
            }
        }

        float pi, pf, pg, po;
        unpack2(my01, pi, pf);
        unpack2(my23, pg, po);
        const float* xr = xg + (size_t)t * Bz * G4 + (size_t)lane * G4;
        pi += xr[j];
        pf += xr[Hz + j];
        pg += xr[2 * Hz + j];
        po += xr[3 * Hz + j];

        float si = 1.0f / (1.0f + expf(-pi));
        float sf = 1.0f / (1.0f + expf(-pf));
        float so = 1.0f / (1.0f + expf(-po));
        creg = sf * creg + si * tanhf(pg);
        float hn = so * tanhf(creg);
        hout[(size_t)t * Bz * Hz + (size_t)lane * Hz + j] = hn;

        grid_sync();
    }
}

// ---------------------------------------------------------------------------
extern "C" void kernel_launch(void* const* d_in, const int* in_sizes, int n_in,
                              void* d_out, int out_size) {
    (void)in_sizes; (void)n_in; (void)out_size;
    const float* x     = (const float*)d_in[0];
    const float* W_ih0 = (const float*)d_in[1];
    const float* W_hh0 = (const float*)d_in[2];
    const float* b_ih0 = (const float*)d_in[3];
    const float* b_hh0 = (const float*)d_in[4];
    const float* W_ih1 = (const float*)d_in[5];
    const float* W_hh1 = (const float*)d_in[6];
    const float* b_ih1 = (const float*)d_in[7];
    const float* b_hh1 = (const float*)d_in[8];
    const float* W_fc  = (const float*)d_in[9];
    const float* b_fc  = (const float*)d_in[10];
    float* out = (float*)d_out;

    float *xt, *xg, *h1, *h2;
    cudaGetSymbolAddress((void**)&xt, g_xt);
    cudaGetSymbolAddress((void**)&xg, g_xg);
    cudaGetSymbolAddress((void**)&h1, g_h1);
    cudaGetSymbolAddress((void**)&h2, g_h2);

    const int REC_SMEM = Bz * Hz * (int)sizeof(float);  // 128KB
    cudaFuncSetAttribute(lstm_recurrence,
                         cudaFuncAttributeMaxDynamicSharedMemorySize, REC_SMEM);

    // x -> time-major
    transpose_x<<<4096, 256>>>((const float4*)x, (float4*)xt);

    // layer 0 input GEMM + persistent recurrence
    sgemm_tn<0><<<dim3(G4 / 128, (Tz * Bz) / 128), 256>>>(xt, W_ih0, b_ih0, b_hh0,
                                                          xg, Tz * Bz, G4, Iz);
    lstm_recurrence<<<128, 256, REC_SMEM>>>(xg, W_hh0, h1);

    // layer 1 input GEMM + persistent recurrence
    sgemm_tn<0><<<dim3(G4 / 128, (Tz * Bz) / 128), 256>>>(h1, W_ih1, b_ih1, b_hh1,
                                                          xg, Tz * Bz, G4, Hz);
    lstm_recurrence<<<128, 256, REC_SMEM>>>(xg, W_hh1, h2);

    // FC over truncated sequence: out[b,t,o], m = b*500 + t -> [16000,512]
    sgemm_tn<1><<<dim3(Oz / 128, (Bz * TR) / 128), 256>>>(h2, W_fc, b_fc, nullptr,
                                                          out, Bz * TR, Oz, Hz);
}

// round 8
// speedup vs baseline: 1.1642x; 1.1642x over previous
#include <cuda_runtime.h>
#include <math.h>

#define Bz 32
#define Tz 512
#define Iz 256
#define Hz 1024
#define G4 4096
#define Oz 512
#define TR 500

typedef unsigned long long ull;

// ---- packed f32x2 helpers (sm_103a) ----
__device__ __forceinline__ ull pack2(float x, float y) {
    ull r; asm("mov.b64 %0, {%1,%2};" : "=l"(r) : "f"(x), "f"(y)); return r;
}
__device__ __forceinline__ void unpack2(ull v, float& x, float& y) {
    asm("mov.b64 {%0,%1}, %2;" : "=f"(x), "=f"(y) : "l"(v));
}
__device__ __forceinline__ void fma2(ull& d, ull a, ull b) {
    asm("fma.rn.f32x2 %0, %1, %2, %0;" : "+l"(d) : "l"(a), "l"(b));
}
__device__ __forceinline__ ull add2(ull a, ull b) {
    ull r; asm("add.rn.f32x2 %0, %1, %2;" : "=l"(r) : "l"(a), "l"(b)); return r;
}

// ---- scratch (device globals: allocation-free) ----
__device__ __align__(16) float g_xt[Tz * Bz * Iz];
__device__ __align__(16) float g_xg[Tz * Bz * G4];
__device__ __align__(16) float g_h1[Tz * Bz * Hz];
__device__ __align__(16) float g_h2[Tz * Bz * Hz];

// ---- software grid barrier (128 blocks, all co-resident: 1 block/SM) ----
__device__ unsigned g_bar_count = 0;
__device__ volatile unsigned g_bar_gen = 0;

__device__ __forceinline__ void grid_sync() {
    __syncthreads();
    if (threadIdx.x == 0) {
        __threadfence();
        unsigned gen = g_bar_gen;
        if (atomicAdd(&g_bar_count, 1u) == gridDim.x - 1u) {
            g_bar_count = 0;
            __threadfence();
            g_bar_gen = gen + 1u;
        } else {
            while (g_bar_gen == gen) { }
        }
    }
    __syncthreads();
}

// ---------------------------------------------------------------------------
// Transpose x: [B,T,I] -> time-major [T,B,I] (float4)
// ---------------------------------------------------------------------------
__global__ void transpose_x(const float4* __restrict__ x, float4* __restrict__ xt) {
    int idx = blockIdx.x * blockDim.x + threadIdx.x;   // < 1048576
    int i4 = idx & 63;
    int m  = idx >> 6;
    int t  = m >> 5;
    int b  = m & 31;
    xt[idx] = x[(b * Tz + t) * (Iz / 4) + i4];
}

// ---------------------------------------------------------------------------
// SGEMM (TN): C[m][n] = sum_k Arow(m)[k] * W[n][k] + b1[n] (+ b2[n])
// (unchanged from R6 — passing)
// ---------------------------------------------------------------------------
template <int MODE>
__global__ __launch_bounds__(256, 2)
void sgemm_tn(const float* __restrict__ A, const float* __restrict__ W,
              const float* __restrict__ b1, const float* __restrict__ b2,
              float* __restrict__ C, int M, int N, int K) {
    __shared__ __align__(16) float As[16][128];
    __shared__ __align__(16) float Bs[16][128];

    const int tid = threadIdx.x;
    const int ty = tid >> 4, tx = tid & 15;
    const int m0 = blockIdx.y * 128, n0 = blockIdx.x * 128;

    ull acc[4][8];
#pragma unroll
    for (int i = 0; i < 4; i++)
#pragma unroll
        for (int j = 0; j < 8; j++) acc[i][j] = 0ULL;

    const float* arow[2];
    int arr[2], acc4[2];
#pragma unroll
    for (int i = 0; i < 2; i++) {
        int item = tid + 256 * i;
        int r = item >> 2, c4 = item & 3;
        arr[i] = r; acc4[i] = c4;
        int m = m0 + r;
        if (MODE == 1) {
            int bb = m / TR, t = m - bb * TR;
            arow[i] = A + (long long)(t * Bz + bb) * K;
        } else {
            arow[i] = A + (long long)m * K;
        }
    }
    const float* wrow[2];
#pragma unroll
    for (int i = 0; i < 2; i++) wrow[i] = W + (long long)(n0 + arr[i]) * K;

    for (int k0 = 0; k0 < K; k0 += 16) {
        __syncthreads();
#pragma unroll
        for (int i = 0; i < 2; i++) {
            int r = arr[i], c4 = acc4[i];
            float4 va = *(const float4*)(arow[i] + k0 + c4 * 4);
            As[c4 * 4 + 0][r] = va.x; As[c4 * 4 + 1][r] = va.y;
            As[c4 * 4 + 2][r] = va.z; As[c4 * 4 + 3][r] = va.w;
            float4 vb = *(const float4*)(wrow[i] + k0 + c4 * 4);
            Bs[c4 * 4 + 0][r] = vb.x; Bs[c4 * 4 + 1][r] = vb.y;
            Bs[c4 * 4 + 2][r] = vb.z; Bs[c4 * 4 + 3][r] = vb.w;
        }
        __syncthreads();
#pragma unroll
        for (int k = 0; k < 16; k++) {
            ull a2[4];
#pragma unroll
            for (int mp = 0; mp < 4; mp++)
                a2[mp] = *(const ull*)&As[k][ty * 8 + mp * 2];
            float4 bv0 = *(const float4*)&Bs[k][tx * 8];
            float4 bv1 = *(const float4*)&Bs[k][tx * 8 + 4];
            ull bd[8];
            bd[0] = pack2(bv0.x, bv0.x); bd[1] = pack2(bv0.y, bv0.y);
            bd[2] = pack2(bv0.z, bv0.z); bd[3] = pack2(bv0.w, bv0.w);
            bd[4] = pack2(bv1.x, bv1.x); bd[5] = pack2(bv1.y, bv1.y);
            bd[6] = pack2(bv1.z, bv1.z); bd[7] = pack2(bv1.w, bv1.w);
#pragma unroll
            for (int mp = 0; mp < 4; mp++)
#pragma unroll
                for (int n = 0; n < 8; n++) fma2(acc[mp][n], a2[mp], bd[n]);
        }
    }

    float bb[8];
#pragma unroll
    for (int n = 0; n < 8; n++) {
        int col = n0 + tx * 8 + n;
        bb[n] = b1[col] + (b2 ? b2[col] : 0.0f);
    }
#pragma unroll
    for (int mp = 0; mp < 4; mp++) {
        float lo[8], hi[8];
#pragma unroll
        for (int n = 0; n < 8; n++) unpack2(acc[mp][n], lo[n], hi[n]);
        int row0 = m0 + ty * 8 + mp * 2;
        float* c0 = C + (long long)row0 * N + n0 + tx * 8;
        float* c1 = c0 + N;
        float o0[8], o1[8];
#pragma unroll
        for (int n = 0; n < 8; n++) { o0[n] = lo[n] + bb[n]; o1[n] = hi[n] + bb[n]; }
        *(float4*)(c0)     = make_float4(o0[0], o0[1], o0[2], o0[3]);
        *(float4*)(c0 + 4) = make_float4(o0[4], o0[5], o0[6], o0[7]);
        *(float4*)(c1)     = make_float4(o1[0], o1[1], o1[2], o1[3]);
        *(float4*)(c1 + 4) = make_float4(o1[4], o1[5], o1[6], o1[7]);
    }
}

// ---------------------------------------------------------------------------
// Persistent LSTM recurrence (R7 rewrite): k-pair-packed f32x2, zero pack movs.
// 128 blocks x 256 threads; warp u owns hidden unit j = 8*blk + u (all 4 gates).
// Lane owns k-pair slice k = 64m + 2*lane (+0/1): weights live in 64 ull regs.
// Per step: stage h[t-1] -> smem; per batch: 16 LDS.64 + 64 fma2 into 4 gate
// accumulators (each ull = even/odd k partial), fold lo+hi, 2-ull shfl tree.
// b-loop unrolled x2 (8 fma chains) for latency hiding. fma2 pipe is the
// structural floor: 4096 warp-instr x rt2 = 8192 cyc/SMSP/step.
// ---------------------------------------------------------------------------
__global__ __launch_bounds__(256, 1)
void lstm_recurrence(const float* __restrict__ xg,   // [T][B][4H]
                     const float* __restrict__ Whh,  // [4H][H]
                     float* __restrict__ hout) {     // [T][B][H]
    extern __shared__ float sh[];                    // [32][1024] = 128KB
    const int tid = threadIdx.x;
    const int lane = tid & 31;
    const int u = tid >> 5;
    const int j = blockIdx.x * 8 + u;

    // Weights: per gate, 16 ull; wX[m] = (W[gH+j][64m+2*lane], W[..][64m+2*lane+1])
    ull wi[16], wf[16], wg[16], wo[16];
    {
        const ull* Wi = (const ull*)(Whh + (size_t)j * Hz) + lane;
        const ull* Wf = (const ull*)(Whh + (size_t)(Hz + j) * Hz) + lane;
        const ull* Wg = (const ull*)(Whh + (size_t)(2 * Hz + j) * Hz) + lane;
        const ull* Wo = (const ull*)(Whh + (size_t)(3 * Hz + j) * Hz) + lane;
#pragma unroll
        for (int m = 0; m < 16; m++) {
            wi[m] = Wi[32 * m]; wf[m] = Wf[32 * m];
            wg[m] = Wg[32 * m]; wo[m] = Wo[32 * m];
        }
    }

    float creg = 0.0f;                    // c[b=lane][j] register-resident
    float4* shv = (float4*)sh;

    for (int t = 0; t < Tz; t++) {
        // xg loads first: independent of h[t-1], overlap with staging
        const float* xr = xg + (size_t)t * Bz * G4 + (size_t)lane * G4;
        float xi = __ldg(xr + j);
        float xf = __ldg(xr + Hz + j);
        float xgv = __ldg(xr + 2 * Hz + j);
        float xo = __ldg(xr + 3 * Hz + j);

        if (t > 0) {
            const float4* hp = (const float4*)(hout + (size_t)(t - 1) * Bz * Hz);
#pragma unroll 8
            for (int i = 0; i < 32; i++)
                shv[tid + 256 * i] = hp[tid + 256 * i];
        }
        __syncthreads();

        ull my01 = 0ULL, my23 = 0ULL;
        if (t > 0) {
#pragma unroll 1
            for (int b = 0; b < 32; b += 2) {
                ull ai0 = 0, af0 = 0, ag0 = 0, ao0 = 0;
                ull ai1 = 0, af1 = 0, ag1 = 0, ao1 = 0;
                const ull* h0 = (const ull*)(sh + b * Hz) + lane;
                const ull* h1 = h0 + (Hz / 2);
#pragma unroll
                for (int m = 0; m < 16; m++) {
                    ull ha = h0[32 * m];
                    ull hb = h1[32 * m];
                    fma2(ai0, ha, wi[m]); fma2(af0, ha, wf[m]);
                    fma2(ag0, ha, wg[m]); fma2(ao0, ha, wo[m]);
                    fma2(ai1, hb, wi[m]); fma2(af1, hb, wf[m]);
                    fma2(ag1, hb, wg[m]); fma2(ao1, hb, wo[m]);
                }
                // fold even/odd halves -> (i,f),(g,o) packed pairs
                float l, h;
                unpack2(ai0, l, h); float i0 = l + h;
                unpack2(af0, l, h); float f0 = l + h;
                unpack2(ag0, l, h); float g0 = l + h;
                unpack2(ao0, l, h); float o0 = l + h;
                unpack2(ai1, l, h); float i1 = l + h;
                unpack2(af1, l, h); float f1 = l + h;
                unpack2(ag1, l, h); float g1 = l + h;
                unpack2(ao1, l, h); float o1 = l + h;
                ull p01a = pack2(i0, f0), p23a = pack2(g0, o0);
                ull p01b = pack2(i1, f1), p23b = pack2(g1, o1);
#pragma unroll
                for (int off = 16; off > 0; off >>= 1) {
                    p01a = add2(p01a, __shfl_xor_sync(0xffffffffu, p01a, off));
                    p23a = add2(p23a, __shfl_xor_sync(0xffffffffu, p23a, off));
                    p01b = add2(p01b, __shfl_xor_sync(0xffffffffu, p01b, off));
                    p23b = add2(p23b, __shfl_xor_sync(0xffffffffu, p23b, off));
                }
                if (lane == b)     { my01 = p01a; my23 = p23a; }
                if (lane == b + 1) { my01 = p01b; my23 = p23b; }
            }
        }

        float pi, pf, pg, po;
        unpack2(my01, pi, pf);
        unpack2(my23, pg, po);
        pi += xi; pf += xf; pg += xgv; po += xo;

        float si = 1.0f / (1.0f + expf(-pi));
        float sf = 1.0f / (1.0f + expf(-pf));
        float so = 1.0f / (1.0f + expf(-po));
        creg = sf * creg + si * tanhf(pg);
        float hn = so * tanhf(creg);
        hout[(size_t)t * Bz * Hz + (size_t)lane * Hz + j] = hn;

        grid_sync();
    }
}

// ---------------------------------------------------------------------------
extern "C" void kernel_launch(void* const* d_in, const int* in_sizes, int n_in,
                              void* d_out, int out_size) {
    (void)in_sizes; (void)n_in; (void)out_size;
    const float* x     = (const float*)d_in[0];
    const float* W_ih0 = (const float*)d_in[1];
    const float* W_hh0 = (const float*)d_in[2];
    const float* b_ih0 = (const float*)d_in[3];
    const float* b_hh0 = (const float*)d_in[4];
    const float* W_ih1 = (const float*)d_in[5];
    const float* W_hh1 = (const float*)d_in[6];
    const float* b_ih1 = (const float*)d_in[7];
    const float* b_hh1 = (const float*)d_in[8];
    const float* W_fc  = (const float*)d_in[9];
    const float* b_fc  = (const float*)d_in[10];
    float* out = (float*)d_out;

    float *xt, *xgp, *h1, *h2;
    cudaGetSymbolAddress((void**)&xt, g_xt);
    cudaGetSymbolAddress((void**)&xgp, g_xg);
    cudaGetSymbolAddress((void**)&h1, g_h1);
    cudaGetSymbolAddress((void**)&h2, g_h2);

    const int REC_SMEM = Bz * Hz * (int)sizeof(float);  // 128KB
    cudaFuncSetAttribute(lstm_recurrence,
                         cudaFuncAttributeMaxDynamicSharedMemorySize, REC_SMEM);

    // x -> time-major
    transpose_x<<<4096, 256>>>((const float4*)x, (float4*)xt);

    // layer 0: input GEMM + persistent recurrence
    sgemm_tn<0><<<dim3(G4 / 128, (Tz * Bz) / 128), 256>>>(xt, W_ih0, b_ih0, b_hh0,
                                                          xgp, Tz * Bz, G4, Iz);
    lstm_recurrence<<<128, 256, REC_SMEM>>>(xgp, W_hh0, h1);

    // layer 1: input GEMM + persistent recurrence
    sgemm_tn<0><<<dim3(G4 / 128, (Tz * Bz) / 128), 256>>>(h1, W_ih1, b_ih1, b_hh1,
                                                          xgp, Tz * Bz, G4, Hz);
    lstm_recurrence<<<128, 256, REC_SMEM>>>(xgp, W_hh1, h2);

    // FC over truncated sequence: out[b,t,o], m = b*500 + t -> [16000,512]
    sgemm_tn<1><<<dim3(Oz / 128, (Bz * TR) / 128), 256>>>(h2, W_fc, b_fc, nullptr,
                                                          out, Bz * TR, Oz, Hz);
}

// round 9
// speedup vs baseline: 1.3189x; 1.1329x over previous
#include <cuda_runtime.h>
#include <math.h>

#define Bz 32
#define Tz 512
#define Iz 256
#define Hz 1024
#define G4 4096
#define Oz 512
#define TR 500

typedef unsigned long long ull;

// ---- packed f32x2 helpers (sm_103a) ----
__device__ __forceinline__ ull pack2(float x, float y) {
    ull r; asm("mov.b64 %0, {%1,%2};" : "=l"(r) : "f"(x), "f"(y)); return r;
}
__device__ __forceinline__ void unpack2(ull v, float& x, float& y) {
    asm("mov.b64 {%0,%1}, %2;" : "=f"(x), "=f"(y) : "l"(v));
}
__device__ __forceinline__ void fma2(ull& d, ull a, ull b) {
    asm("fma.rn.f32x2 %0, %1, %2, %0;" : "+l"(d) : "l"(a), "l"(b));
}
__device__ __forceinline__ ull add2(ull a, ull b) {
    ull r; asm("add.rn.f32x2 %0, %1, %2;" : "=l"(r) : "l"(a), "l"(b)); return r;
}

__device__ __forceinline__ float sig_f(float x) {
    return __fdividef(1.0f, 1.0f + __expf(-x));
}
__device__ __forceinline__ float tanh_f(float x) {
    return 1.0f - __fdividef(2.0f, __expf(2.0f * x) + 1.0f);
}

// ---- scratch (device globals: allocation-free) ----
__device__ __align__(16) float g_xt[Tz * Bz * Iz];
__device__ __align__(16) float g_xg[Tz * Bz * G4];
__device__ __align__(16) float g_h1[Tz * Bz * Hz];
__device__ __align__(16) float g_h2[Tz * Bz * Hz];

// ---- software grid barrier (128 blocks, all co-resident: 1 block/SM) ----
__device__ unsigned g_bar_count = 0;
__device__ volatile unsigned g_bar_gen = 0;

__device__ __forceinline__ void grid_sync() {
    __syncthreads();
    if (threadIdx.x == 0) {
        __threadfence();
        unsigned gen = g_bar_gen;
        if (atomicAdd(&g_bar_count, 1u) == gridDim.x - 1u) {
            g_bar_count = 0;
            __threadfence();
            g_bar_gen = gen + 1u;
        } else {
            while (g_bar_gen == gen) { }
            __threadfence();
        }
    }
    __syncthreads();
}

// ---------------------------------------------------------------------------
// Transpose x: [B,T,I] -> time-major [T,B,I] (float4)
// ---------------------------------------------------------------------------
__global__ void transpose_x(const float4* __restrict__ x, float4* __restrict__ xt) {
    int idx = blockIdx.x * blockDim.x + threadIdx.x;   // < 1048576
    int i4 = idx & 63;
    int m  = idx >> 6;
    int t  = m >> 5;
    int b  = m & 31;
    xt[idx] = x[(b * Tz + t) * (Iz / 4) + i4];
}

// ---------------------------------------------------------------------------
// SGEMM (TN): unchanged from R6/R7 (passing, fma=58.5%)
// ---------------------------------------------------------------------------
template <int MODE>
__global__ __launch_bounds__(256, 2)
void sgemm_tn(const float* __restrict__ A, const float* __restrict__ W,
              const float* __restrict__ b1, const float* __restrict__ b2,
              float* __restrict__ C, int M, int N, int K) {
    __shared__ __align__(16) float As[16][128];
    __shared__ __align__(16) float Bs[16][128];

    const int tid = threadIdx.x;
    const int ty = tid >> 4, tx = tid & 15;
    const int m0 = blockIdx.y * 128, n0 = blockIdx.x * 128;

    ull acc[4][8];
#pragma unroll
    for (int i = 0; i < 4; i++)
#pragma unroll
        for (int j = 0; j < 8; j++) acc[i][j] = 0ULL;

    const float* arow[2];
    int arr[2], acc4[2];
#pragma unroll
    for (int i = 0; i < 2; i++) {
        int item = tid + 256 * i;
        int r = item >> 2, c4 = item & 3;
        arr[i] = r; acc4[i] = c4;
        int m = m0 + r;
        if (MODE == 1) {
            int bb = m / TR, t = m - bb * TR;
            arow[i] = A + (long long)(t * Bz + bb) * K;
        } else {
            arow[i] = A + (long long)m * K;
        }
    }
    const float* wrow[2];
#pragma unroll
    for (int i = 0; i < 2; i++) wrow[i] = W + (long long)(n0 + arr[i]) * K;

    for (int k0 = 0; k0 < K; k0 += 16) {
        __syncthreads();
#pragma unroll
        for (int i = 0; i < 2; i++) {
            int r = arr[i], c4 = acc4[i];
            float4 va = *(const float4*)(arow[i] + k0 + c4 * 4);
            As[c4 * 4 + 0][r] = va.x; As[c4 * 4 + 1][r] = va.y;
            As[c4 * 4 + 2][r] = va.z; As[c4 * 4 + 3][r] = va.w;
            float4 vb = *(const float4*)(wrow[i] + k0 + c4 * 4);
            Bs[c4 * 4 + 0][r] = vb.x; Bs[c4 * 4 + 1][r] = vb.y;
            Bs[c4 * 4 + 2][r] = vb.z; Bs[c4 * 4 + 3][r] = vb.w;
        }
        __syncthreads();
#pragma unroll
        for (int k = 0; k < 16; k++) {
            ull a2[4];
#pragma unroll
            for (int mp = 0; mp < 4; mp++)
                a2[mp] = *(const ull*)&As[k][ty * 8 + mp * 2];
            float4 bv0 = *(const float4*)&Bs[k][tx * 8];
            float4 bv1 = *(const float4*)&Bs[k][tx * 8 + 4];
            ull bd[8];
            bd[0] = pack2(bv0.x, bv0.x); bd[1] = pack2(bv0.y, bv0.y);
            bd[2] = pack2(bv0.z, bv0.z); bd[3] = pack2(bv0.w, bv0.w);
            bd[4] = pack2(bv1.x, bv1.x); bd[5] = pack2(bv1.y, bv1.y);
            bd[6] = pack2(bv1.z, bv1.z); bd[7] = pack2(bv1.w, bv1.w);
#pragma unroll
            for (int mp = 0; mp < 4; mp++)
#pragma unroll
                for (int n = 0; n < 8; n++) fma2(acc[mp][n], a2[mp], bd[n]);
        }
    }

    float bb[8];
#pragma unroll
    for (int n = 0; n < 8; n++) {
        int col = n0 + tx * 8 + n;
        bb[n] = b1[col] + (b2 ? b2[col] : 0.0f);
    }
#pragma unroll
    for (int mp = 0; mp < 4; mp++) {
        float lo[8], hi[8];
#pragma unroll
        for (int n = 0; n < 8; n++) unpack2(acc[mp][n], lo[n], hi[n]);
        int row0 = m0 + ty * 8 + mp * 2;
        float* c0 = C + (long long)row0 * N + n0 + tx * 8;
        float* c1 = c0 + N;
        float o0[8], o1[8];
#pragma unroll
        for (int n = 0; n < 8; n++) { o0[n] = lo[n] + bb[n]; o1[n] = hi[n] + bb[n]; }
        *(float4*)(c0)     = make_float4(o0[0], o0[1], o0[2], o0[3]);
        *(float4*)(c0 + 4) = make_float4(o0[4], o0[5], o0[6], o0[7]);
        *(float4*)(c1)     = make_float4(o1[0], o1[1], o1[2], o1[3]);
        *(float4*)(c1 + 4) = make_float4(o1[4], o1[5], o1[6], o1[7]);
    }
}

// ---------------------------------------------------------------------------
// Persistent LSTM recurrence, R8: ring (systolic) reduction.
// 128 blocks x 256 threads; warp u owns hidden unit j = 8*blk + u (all 4 gates).
// Lane owns k-slice {128m + 4*lane .. +3 : m=0..7} -> weights = 64 ull regs.
// Ring: at step s, lane l computes the 4-gate partial for batch (l+s)&31 over
// its k-slice (8 LDS.128 + 64 fma2), folds to (i,f),(g,o) ull pair, adds into
// the rotating accumulators, rotates by one lane (4 SHFL.32). After 32 steps
// the accumulator for batch b sits on lane b. SHFL count: 128/warp/step
// (was 640 with the butterfly) -> MIO drops from ~13K to ~9.2K cyc/SM/step.
// ---------------------------------------------------------------------------
__global__ __launch_bounds__(256, 1)
void lstm_recurrence(const float* __restrict__ xg,   // [T][B][4H]
                     const float* __restrict__ Whh,  // [4H][H]
                     float* __restrict__ hout) {     // [T][B][H]
    extern __shared__ float sh[];                    // [32][1024] = 128KB
    const int tid = threadIdx.x;
    const int lane = tid & 31;
    const int u = tid >> 5;
    const int j = blockIdx.x * 8 + u;
    const int srcl = (lane + 1) & 31;

    // Weights: per gate 16 ull; w[2m],w[2m+1] = k-pairs {128m+4l,+1},{128m+4l+2,+3}
    ull wi[16], wf[16], wg[16], wo[16];
    {
        const ulonglong2* Wi = (const ulonglong2*)(Whh + (size_t)j * Hz) + lane;
        const ulonglong2* Wf = (const ulonglong2*)(Whh + (size_t)(Hz + j) * Hz) + lane;
        const ulonglong2* Wg = (const ulonglong2*)(Whh + (size_t)(2 * Hz + j) * Hz) + lane;
        const ulonglong2* Wo = (const ulonglong2*)(Whh + (size_t)(3 * Hz + j) * Hz) + lane;
#pragma unroll
        for (int m = 0; m < 8; m++) {
            ulonglong2 a = Wi[32 * m]; wi[2 * m] = a.x; wi[2 * m + 1] = a.y;
            ulonglong2 b = Wf[32 * m]; wf[2 * m] = b.x; wf[2 * m + 1] = b.y;
            ulonglong2 c = Wg[32 * m]; wg[2 * m] = c.x; wg[2 * m + 1] = c.y;
            ulonglong2 d = Wo[32 * m]; wo[2 * m] = d.x; wo[2 * m + 1] = d.y;
        }
    }

    float creg = 0.0f;                    // c[b=lane][j] register-resident
    float4* shv = (float4*)sh;

    for (int t = 0; t < Tz; t++) {
        // xg loads first: independent of h[t-1], overlap with staging
        const float* xr = xg + (size_t)t * Bz * G4 + (size_t)lane * G4;
        float xi = __ldg(xr + j);
        float xf = __ldg(xr + Hz + j);
        float xgv = __ldg(xr + 2 * Hz + j);
        float xo = __ldg(xr + 3 * Hz + j);

        if (t > 0) {
            const float4* hp = (const float4*)(hout + (size_t)(t - 1) * Bz * Hz);
#pragma unroll 8
            for (int i = 0; i < 32; i++)
                shv[tid + 256 * i] = hp[tid + 256 * i];
        }
        __syncthreads();

        ull r01 = 0ULL, r23 = 0ULL;       // rotating (i,f) / (g,o) accumulators
        if (t > 0) {
#pragma unroll 2
            for (int s = 0; s < 32; s++) {
                const int b = (lane + s) & 31;
                const ulonglong2* hb = (const ulonglong2*)(sh + b * Hz) + lane;
                ull ai = 0, af = 0, ag = 0, ao = 0;
#pragma unroll
                for (int m = 0; m < 8; m++) {
                    ulonglong2 h2 = hb[32 * m];
                    fma2(ai, h2.x, wi[2 * m]);     fma2(af, h2.x, wf[2 * m]);
                    fma2(ag, h2.x, wg[2 * m]);     fma2(ao, h2.x, wo[2 * m]);
                    fma2(ai, h2.y, wi[2 * m + 1]); fma2(af, h2.y, wf[2 * m + 1]);
                    fma2(ag, h2.y, wg[2 * m + 1]); fma2(ao, h2.y, wo[2 * m + 1]);
                }
                float l0, h0;
                unpack2(ai, l0, h0); float iv = l0 + h0;
                unpack2(af, l0, h0); float fv = l0 + h0;
                unpack2(ag, l0, h0); float gv = l0 + h0;
                unpack2(ao, l0, h0); float ov = l0 + h0;
                r01 = add2(r01, pack2(iv, fv));
                r23 = add2(r23, pack2(gv, ov));
                r01 = __shfl_sync(0xffffffffu, r01, srcl);
                r23 = __shfl_sync(0xffffffffu, r23, srcl);
            }
        }

        // r01/r23 now hold the full recurrent gate sums for batch b = lane
        float pi, pf, pg, po;
        unpack2(r01, pi, pf);
        unpack2(r23, pg, po);
        pi += xi; pf += xf; pg += xgv; po += xo;

        float si = sig_f(pi);
        float sf = sig_f(pf);
        float so = sig_f(po);
        creg = sf * creg + si * tanh_f(pg);
        float hn = so * tanh_f(creg);
        hout[(size_t)t * Bz * Hz + (size_t)lane * Hz + j] = hn;

        grid_sync();
    }
}

// ---------------------------------------------------------------------------
extern "C" void kernel_launch(void* const* d_in, const int* in_sizes, int n_in,
                              void* d_out, int out_size) {
    (void)in_sizes; (void)n_in; (void)out_size;
    const float* x     = (const float*)d_in[0];
    const float* W_ih0 = (const float*)d_in[1];
    const float* W_hh0 = (const float*)d_in[2];
    const float* b_ih0 = (const float*)d_in[3];
    const float* b_hh0 = (const float*)d_in[4];
    const float* W_ih1 = (const float*)d_in[5];
    const float* W_hh1 = (const float*)d_in[6];
    const float* b_ih1 = (const float*)d_in[7];
    const float* b_hh1 = (const float*)d_in[8];
    const float* W_fc  = (const float*)d_in[9];
    const float* b_fc  = (const float*)d_in[10];
    float* out = (float*)d_out;

    float *xt, *xgp, *h1, *h2;
    cudaGetSymbolAddress((void**)&xt, g_xt);
    cudaGetSymbolAddress((void**)&xgp, g_xg);
    cudaGetSymbolAddress((void**)&h1, g_h1);
    cudaGetSymbolAddress((void**)&h2, g_h2);

    const int REC_SMEM = Bz * Hz * (int)sizeof(float);  // 128KB
    cudaFuncSetAttribute(lstm_recurrence,
                         cudaFuncAttributeMaxDynamicSharedMemorySize, REC_SMEM);

    // x -> time-major
    transpose_x<<<4096, 256>>>((const float4*)x, (float4*)xt);

    // layer 0: input GEMM + persistent recurrence
    sgemm_tn<0><<<dim3(G4 / 128, (Tz * Bz) / 128), 256>>>(xt, W_ih0, b_ih0, b_hh0,
                                                          xgp, Tz * Bz, G4, Iz);
    lstm_recurrence<<<128, 256, REC_SMEM>>>(xgp, W_hh0, h1);

    // layer 1: input GEMM + persistent recurrence
    sgemm_tn<0><<<dim3(G4 / 128, (Tz * Bz) / 128), 256>>>(h1, W_ih1, b_ih1, b_hh1,
                                                          xgp, Tz * Bz, G4, Hz);
    lstm_recurrence<<<128, 256, REC_SMEM>>>(xgp, W_hh1, h2);

    // FC over truncated sequence: out[b,t,o], m = b*500 + t -> [16000,512]
    sgemm_tn<1><<<dim3(Oz / 128, (Bz * TR) / 128), 256>>>(h2, W_fc, b_fc, nullptr,
                                                          out, Bz * TR, Oz, Hz);
}

// round 10
// speedup vs baseline: 1.4327x; 1.0863x over previous
#include <cuda_runtime.h>
#include <math.h>

#define Bz 32
#define Tz 512
#define Iz 256
#define Hz 1024
#define G4 4096
#define Oz 512
#define TR 500

typedef unsigned long long ull;

// ---- packed f32x2 helpers (sm_103a) ----
__device__ __forceinline__ ull pack2(float x, float y) {
    ull r; asm("mov.b64 %0, {%1,%2};" : "=l"(r) : "f"(x), "f"(y)); return r;
}
__device__ __forceinline__ void unpack2(ull v, float& x, float& y) {
    asm("mov.b64 {%0,%1}, %2;" : "=f"(x), "=f"(y) : "l"(v));
}
__device__ __forceinline__ void fma2(ull& d, ull a, ull b) {
    asm("fma.rn.f32x2 %0, %1, %2, %0;" : "+l"(d) : "l"(a), "l"(b));
}
__device__ __forceinline__ ull add2(ull a, ull b) {
    ull r; asm("add.rn.f32x2 %0, %1, %2;" : "=l"(r) : "l"(a), "l"(b)); return r;
}

__device__ __forceinline__ float sig_f(float x) {
    return __fdividef(1.0f, 1.0f + __expf(-x));
}
__device__ __forceinline__ float tanh_f(float x) {
    return 1.0f - __fdividef(2.0f, __expf(2.0f * x) + 1.0f);
}

// cp.async 16B: global -> shared, L2-only path
__device__ __forceinline__ void cp16(unsigned smem_addr, const void* gptr) {
    asm volatile("cp.async.cg.shared.global [%0], [%1], 16;"
                 :: "r"(smem_addr), "l"(gptr) : "memory");
}

// ---- scratch (device globals: allocation-free) ----
__device__ __align__(16) float g_xt[Tz * Bz * Iz];
__device__ __align__(16) float g_xg[Tz * Bz * G4];
__device__ __align__(16) float g_h1[Tz * Bz * Hz];
__device__ __align__(16) float g_h2[Tz * Bz * Hz];

// ---- software grid barrier (128 blocks, all co-resident: 1 block/SM) ----
__device__ unsigned g_bar_count = 0;
__device__ volatile unsigned g_bar_gen = 0;

__device__ __forceinline__ void grid_sync() {
    __syncthreads();
    if (threadIdx.x == 0) {
        __threadfence();
        unsigned gen = g_bar_gen;
        if (atomicAdd(&g_bar_count, 1u) == gridDim.x - 1u) {
            g_bar_count = 0;
            __threadfence();
            g_bar_gen = gen + 1u;
        } else {
            while (g_bar_gen == gen) { }
            __threadfence();
        }
    }
    __syncthreads();
}

// ---------------------------------------------------------------------------
// Transpose x: [B,T,I] -> time-major [T,B,I] (float4)
// ---------------------------------------------------------------------------
__global__ void transpose_x(const float4* __restrict__ x, float4* __restrict__ xt) {
    int idx = blockIdx.x * blockDim.x + threadIdx.x;   // < 1048576
    int i4 = idx & 63;
    int m  = idx >> 6;
    int t  = m >> 5;
    int b  = m & 31;
    xt[idx] = x[(b * Tz + t) * (Iz / 4) + i4];
}

// ---------------------------------------------------------------------------
// SGEMM (TN), R9: register-staged prefetch of the next BK=16 tile so the LDG
// latency hides behind the current tile's 512 fma-pipe cycles (was exposed:
// fma=58.6%). Same math/layout as R6-R8 otherwise.
// ---------------------------------------------------------------------------
template <int MODE>
__global__ __launch_bounds__(256, 2)
void sgemm_tn(const float* __restrict__ A, const float* __restrict__ W,
              const float* __restrict__ b1, const float* __restrict__ b2,
              float* __restrict__ C, int M, int N, int K) {
    __shared__ __align__(16) float As[16][128];
    __shared__ __align__(16) float Bs[16][128];

    const int tid = threadIdx.x;
    const int ty = tid >> 4, tx = tid & 15;
    const int m0 = blockIdx.y * 128, n0 = blockIdx.x * 128;

    ull acc[4][8];
#pragma unroll
    for (int i = 0; i < 4; i++)
#pragma unroll
        for (int j = 0; j < 8; j++) acc[i][j] = 0ULL;

    const float* arow[2];
    int arr[2], acc4[2];
#pragma unroll
    for (int i = 0; i < 2; i++) {
        int item = tid + 256 * i;
        int r = item >> 2, c4 = item & 3;
        arr[i] = r; acc4[i] = c4;
        int m = m0 + r;
        if (MODE == 1) {
            int bb = m / TR, t = m - bb * TR;
            arow[i] = A + (long long)(t * Bz + bb) * K;
        } else {
            arow[i] = A + (long long)m * K;
        }
    }
    const float* wrow[2];
#pragma unroll
    for (int i = 0; i < 2; i++) wrow[i] = W + (long long)(n0 + arr[i]) * K;

    // preload tile 0 into regs, stage to smem
    float4 va[2], vb[2];
#pragma unroll
    for (int i = 0; i < 2; i++) {
        va[i] = *(const float4*)(arow[i] + acc4[i] * 4);
        vb[i] = *(const float4*)(wrow[i] + acc4[i] * 4);
    }
#pragma unroll
    for (int i = 0; i < 2; i++) {
        int r = arr[i], c4 = acc4[i];
        As[c4 * 4 + 0][r] = va[i].x; As[c4 * 4 + 1][r] = va[i].y;
        As[c4 * 4 + 2][r] = va[i].z; As[c4 * 4 + 3][r] = va[i].w;
        Bs[c4 * 4 + 0][r] = vb[i].x; Bs[c4 * 4 + 1][r] = vb[i].y;
        Bs[c4 * 4 + 2][r] = vb[i].z; Bs[c4 * 4 + 3][r] = vb[i].w;
    }
    __syncthreads();

    const int KT = K >> 4;
    for (int kt = 0; kt < KT; kt++) {
        // prefetch next tile into registers (overlaps with compute below)
        if (kt + 1 < KT) {
            int k0n = (kt + 1) << 4;
#pragma unroll
            for (int i = 0; i < 2; i++) {
                va[i] = *(const float4*)(arow[i] + k0n + acc4[i] * 4);
                vb[i] = *(const float4*)(wrow[i] + k0n + acc4[i] * 4);
            }
        }
#pragma unroll
        for (int k = 0; k < 16; k++) {
            ull a2[4];
#pragma unroll
            for (int mp = 0; mp < 4; mp++)
                a2[mp] = *(const ull*)&As[k][ty * 8 + mp * 2];
            float4 bv0 = *(const float4*)&Bs[k][tx * 8];
            float4 bv1 = *(const float4*)&Bs[k][tx * 8 + 4];
            ull bd[8];
            bd[0] = pack2(bv0.x, bv0.x); bd[1] = pack2(bv0.y, bv0.y);
            bd[2] = pack2(bv0.z, bv0.z); bd[3] = pack2(bv0.w, bv0.w);
            bd[4] = pack2(bv1.x, bv1.x); bd[5] = pack2(bv1.y, bv1.y);
            bd[6] = pack2(bv1.z, bv1.z); bd[7] = pack2(bv1.w, bv1.w);
#pragma unroll
            for (int mp = 0; mp < 4; mp++)
#pragma unroll
                for (int n = 0; n < 8; n++) fma2(acc[mp][n], a2[mp], bd[n]);
        }
        if (kt + 1 < KT) {
            __syncthreads();
#pragma unroll
            for (int i = 0; i < 2; i++) {
                int r = arr[i], c4 = acc4[i];
                As[c4 * 4 + 0][r] = va[i].x; As[c4 * 4 + 1][r] = va[i].y;
                As[c4 * 4 + 2][r] = va[i].z; As[c4 * 4 + 3][r] = va[i].w;
                Bs[c4 * 4 + 0][r] = vb[i].x; Bs[c4 * 4 + 1][r] = vb[i].y;
                Bs[c4 * 4 + 2][r] = vb[i].z; Bs[c4 * 4 + 3][r] = vb[i].w;
            }
            __syncthreads();
        }
    }

    float bb[8];
#pragma unroll
    for (int n = 0; n < 8; n++) {
        int col = n0 + tx * 8 + n;
        bb[n] = b1[col] + (b2 ? b2[col] : 0.0f);
    }
#pragma unroll
    for (int mp = 0; mp < 4; mp++) {
        float lo[8], hi[8];
#pragma unroll
        for (int n = 0; n < 8; n++) unpack2(acc[mp][n], lo[n], hi[n]);
        int row0 = m0 + ty * 8 + mp * 2;
        float* c0 = C + (long long)row0 * N + n0 + tx * 8;
        float* c1 = c0 + N;
        float o0[8], o1[8];
#pragma unroll
        for (int n = 0; n < 8; n++) { o0[n] = lo[n] + bb[n]; o1[n] = hi[n] + bb[n]; }
        *(float4*)(c0)     = make_float4(o0[0], o0[1], o0[2], o0[3]);
        *(float4*)(c0 + 4) = make_float4(o0[4], o0[5], o0[6], o0[7]);
        *(float4*)(c1)     = make_float4(o1[0], o1[1], o1[2], o1[3]);
        *(float4*)(c1 + 4) = make_float4(o1[4], o1[5], o1[6], o1[7]);
    }
}

// ---------------------------------------------------------------------------
// Persistent LSTM recurrence, R9: ring reduction (R8) + cp.async staging.
// cp.async.cg copies h[t-1] global->smem directly (no LDG->reg->STS), removing
// the 1024-cyc STS crossbar serialization at the top of every step.
// ---------------------------------------------------------------------------
__global__ __launch_bounds__(256, 1)
void lstm_recurrence(const float* __restrict__ xg,   // [T][B][4H]
                     const float* __restrict__ Whh,  // [4H][H]
                     float* __restrict__ hout) {     // [T][B][H]
    extern __shared__ float sh[];                    // [32][1024] = 128KB
    const int tid = threadIdx.x;
    const int lane = tid & 31;
    const int u = tid >> 5;
    const int j = blockIdx.x * 8 + u;
    const int srcl = (lane + 1) & 31;

    unsigned sh_u32;
    asm("{ .reg .u64 t0; cvta.to.shared.u64 t0, %1; cvt.u32.u64 %0, t0; }"
        : "=r"(sh_u32) : "l"(sh));

    // Weights: per gate 16 ull; w[2m],w[2m+1] = k-pairs {128m+4l,+1},{128m+4l+2,+3}
    ull wi[16], wf[16], wg[16], wo[16];
    {
        const ulonglong2* Wi = (const ulonglong2*)(Whh + (size_t)j * Hz) + lane;
        const ulonglong2* Wf = (const ulonglong2*)(Whh + (size_t)(Hz + j) * Hz) + lane;
        const ulonglong2* Wg = (const ulonglong2*)(Whh + (size_t)(2 * Hz + j) * Hz) + lane;
        const ulonglong2* Wo = (const ulonglong2*)(Whh + (size_t)(3 * Hz + j) * Hz) + lane;
#pragma unroll
        for (int m = 0; m < 8; m++) {
            ulonglong2 a = Wi[32 * m]; wi[2 * m] = a.x; wi[2 * m + 1] = a.y;
            ulonglong2 b = Wf[32 * m]; wf[2 * m] = b.x; wf[2 * m + 1] = b.y;
            ulonglong2 c = Wg[32 * m]; wg[2 * m] = c.x; wg[2 * m + 1] = c.y;
            ulonglong2 d = Wo[32 * m]; wo[2 * m] = d.x; wo[2 * m + 1] = d.y;
        }
    }

    float creg = 0.0f;                    // c[b=lane][j] register-resident

    for (int t = 0; t < Tz; t++) {
        // xg loads first: independent of h[t-1], overlap with staging
        const float* xr = xg + (size_t)t * Bz * G4 + (size_t)lane * G4;
        float xi = __ldg(xr + j);
        float xf = __ldg(xr + Hz + j);
        float xgv = __ldg(xr + 2 * Hz + j);
        float xo = __ldg(xr + 3 * Hz + j);

        if (t > 0) {
            const float* hp = hout + (size_t)(t - 1) * Bz * Hz;
#pragma unroll
            for (int i = 0; i < 32; i++) {
                int idx = tid + 256 * i;
                cp16(sh_u32 + (unsigned)idx * 16u, hp + (size_t)idx * 4);
            }
            asm volatile("cp.async.commit_group;" ::: "memory");
            asm volatile("cp.async.wait_group 0;" ::: "memory");
        }
        __syncthreads();

        ull r01 = 0ULL, r23 = 0ULL;       // rotating (i,f) / (g,o) accumulators
        if (t > 0) {
#pragma unroll 2
            for (int s = 0; s < 32; s++) {
                const int b = (lane + s) & 31;
                const ulonglong2* hb = (const ulonglong2*)(sh + b * Hz) + lane;
                ull ai = 0, af = 0, ag = 0, ao = 0;
#pragma unroll
                for (int m = 0; m < 8; m++) {
                    ulonglong2 h2 = hb[32 * m];
                    fma2(ai, h2.x, wi[2 * m]);     fma2(af, h2.x, wf[2 * m]);
                    fma2(ag, h2.x, wg[2 * m]);     fma2(ao, h2.x, wo[2 * m]);
                    fma2(ai, h2.y, wi[2 * m + 1]); fma2(af, h2.y, wf[2 * m + 1]);
                    fma2(ag, h2.y, wg[2 * m + 1]); fma2(ao, h2.y, wo[2 * m + 1]);
                }
                float l0, h0;
                unpack2(ai, l0, h0); float iv = l0 + h0;
                unpack2(af, l0, h0); float fv = l0 + h0;
                unpack2(ag, l0, h0); float gv = l0 + h0;
                unpack2(ao, l0, h0); float ov = l0 + h0;
                r01 = add2(r01, pack2(iv, fv));
                r23 = add2(r23, pack2(gv, ov));
                r01 = __shfl_sync(0xffffffffu, r01, srcl);
                r23 = __shfl_sync(0xffffffffu, r23, srcl);
            }
        }

        // r01/r23 now hold the full recurrent gate sums for batch b = lane
        float pi, pf, pg, po;
        unpack2(r01, pi, pf);
        unpack2(r23, pg, po);
        pi += xi; pf += xf; pg += xgv; po += xo;

        float si = sig_f(pi);
        float sf = sig_f(pf);
        float so = sig_f(po);
        creg = sf * creg + si * tanh_f(pg);
        float hn = so * tanh_f(creg);
        hout[(size_t)t * Bz * Hz + (size_t)lane * Hz + j] = hn;

        grid_sync();
    }
}

// ---------------------------------------------------------------------------
extern "C" void kernel_launch(void* const* d_in, const int* in_sizes, int n_in,
                              void* d_out, int out_size) {
    (void)in_sizes; (void)n_in; (void)out_size;
    const float* x     = (const float*)d_in[0];
    const float* W_ih0 = (const float*)d_in[1];
    const float* W_hh0 = (const float*)d_in[2];
    const float* b_ih0 = (const float*)d_in[3];
    const float* b_hh0 = (const float*)d_in[4];
    const float* W_ih1 = (const float*)d_in[5];
    const float* W_hh1 = (const float*)d_in[6];
    const float* b_ih1 = (const float*)d_in[7];
    const float* b_hh1 = (const float*)d_in[8];
    const float* W_fc  = (const float*)d_in[9];
    const float* b_fc  = (const float*)d_in[10];
    float* out = (float*)d_out;

    float *xt, *xgp, *h1, *h2;
    cudaGetSymbolAddress((void**)&xt, g_xt);
    cudaGetSymbolAddress((void**)&xgp, g_xg);
    cudaGetSymbolAddress((void**)&h1, g_h1);
    cudaGetSymbolAddress((void**)&h2, g_h2);

    const int REC_SMEM = Bz * Hz * (int)sizeof(float);  // 128KB
    cudaFuncSetAttribute(lstm_recurrence,
                         cudaFuncAttributeMaxDynamicSharedMemorySize, REC_SMEM);

    // x -> time-major
    transpose_x<<<4096, 256>>>((const float4*)x, (float4*)xt);

    // layer 0: input GEMM + persistent recurrence
    sgemm_tn<0><<<dim3(G4 / 128, (Tz * Bz) / 128), 256>>>(xt, W_ih0, b_ih0, b_hh0,
                                                          xgp, Tz * Bz, G4, Iz);
    lstm_recurrence<<<128, 256, REC_SMEM>>>(xgp, W_hh0, h1);

    // layer 1: input GEMM + persistent recurrence
    sgemm_tn<0><<<dim3(G4 / 128, (Tz * Bz) / 128), 256>>>(h1, W_ih1, b_ih1, b_hh1,
                                                          xgp, Tz * Bz, G4, Hz);
    lstm_recurrence<<<128, 256, REC_SMEM>>>(xgp, W_hh1, h2);

    // FC over truncated sequence: out[b,t,o], m = b*500 + t -> [16000,512]
    sgemm_tn<1><<<dim3(Oz / 128, (Bz * TR) / 128), 256>>>(h2, W_fc, b_fc, nullptr,
                                                          out, Bz * TR, Oz, Hz);
}